// round 1
// baseline (speedup 1.0000x reference)
#include <cuda_runtime.h>

#define NN 100000
#define EE 1600000
#define DD 128

// ---------------- static device scratch (no allocation allowed) ----------------
__device__ float g_agg[NN * DD];      // SpMM output / GEMM input
__device__ float g_h[NN * DD];        // layer-1 output
__device__ int   g_outdeg[NN];
__device__ int   g_indeg[NN];
__device__ int   g_rowptr[NN + 1];
__device__ int   g_cursor[NN];
__device__ int   g_colidx[EE];
__device__ float g_inv[NN];

// ---------------- build: degrees ----------------
__global__ void k_init(int N) {
    int i = blockIdx.x * blockDim.x + threadIdx.x;
    if (i < N) { g_outdeg[i] = 0; g_indeg[i] = 0; }
}

__global__ void k_deg(const int* __restrict__ src, const int* __restrict__ dst, int E) {
    int e = blockIdx.x * blockDim.x + threadIdx.x;
    if (e < E) {
        atomicAdd(&g_outdeg[src[e]], 1);
        atomicAdd(&g_indeg[dst[e]], 1);
    }
}

__global__ void k_inv(int N) {
    int i = blockIdx.x * blockDim.x + threadIdx.x;
    if (i < N) {
        int d = g_outdeg[i];
        g_inv[i] = 1.0f / (float)(d > 1 ? d : 1);
    }
}

// ---------------- build: exclusive scan of in-degrees (single block) ----------------
__global__ void k_scan(int N, int E) {
    __shared__ int s_w[32];
    __shared__ int s_carry;
    int tid = threadIdx.x, lane = tid & 31, wid = tid >> 5;
    if (tid == 0) s_carry = 0;
    __syncthreads();
    int nCh = (N + 1023) >> 10;
    for (int c = 0; c < nCh; c++) {
        int i = (c << 10) + tid;
        int v = (i < N) ? g_indeg[i] : 0;
        int incl = v;
#pragma unroll
        for (int off = 1; off < 32; off <<= 1) {
            int t = __shfl_up_sync(0xffffffffu, incl, off);
            if (lane >= off) incl += t;
        }
        if (lane == 31) s_w[wid] = incl;
        __syncthreads();
        if (wid == 0) {
            int s = s_w[lane];
            int si = s;
#pragma unroll
            for (int off = 1; off < 32; off <<= 1) {
                int t = __shfl_up_sync(0xffffffffu, si, off);
                if (lane >= off) si += t;
            }
            s_w[lane] = si - s;  // exclusive prefix of warp sums
        }
        __syncthreads();
        int excl = incl - v + s_w[wid] + s_carry;
        if (i < N) { g_rowptr[i] = excl; g_cursor[i] = excl; }
        __syncthreads();
        if (tid == 1023) s_carry += s_w[31] + incl;  // += block total
        __syncthreads();
    }
    if (tid == 0) g_rowptr[N] = E;
}

// ---------------- build: scatter edges into CSR ----------------
__global__ void k_scatter(const int* __restrict__ src, const int* __restrict__ dst, int E) {
    int e = blockIdx.x * blockDim.x + threadIdx.x;
    if (e < E) {
        int p = atomicAdd(&g_cursor[dst[e]], 1);
        g_colidx[p] = src[e];
    }
}

// ---------------- SpMM gather: out[dst] = sum_{src in-edges} x[src] * inv[src] ----------------
// blockDim = (32, 8): one warp per destination node, float4 per lane (128 floats).
__global__ void k_gather(const float4* __restrict__ xin, float4* __restrict__ out, int N) {
    int lane = threadIdx.x;
    int node = blockIdx.x * blockDim.y + threadIdx.y;
    if (node >= N) return;
    int beg = g_rowptr[node], end = g_rowptr[node + 1];
    float4 acc = make_float4(0.f, 0.f, 0.f, 0.f);
    for (int e = beg; e < end; e++) {
        int s = g_colidx[e];
        float sc = g_inv[s];
        float4 v = xin[s * 32 + lane];
        acc.x += v.x * sc;
        acc.y += v.y * sc;
        acc.z += v.z * sc;
        acc.w += v.w * sc;
    }
    out[node * 32 + lane] = acc;
}

// ---------------- dense GEMM + bias + PReLU ----------------
// C[row] = prelu(A[row] @ W + b). 256 threads, 64 rows/block.
// W (128x128, 64KB) + A tile (64x128, 32KB) in dynamic smem = 96KB.
// Thread (cx,rx): cx = 4-col group (float4), rx = 8-row group. acc = 8x float4.
__global__ void k_gemm(const float* __restrict__ A, const float* __restrict__ W,
                       const float* __restrict__ b, const float* __restrict__ pa,
                       float* __restrict__ out, int N) {
    extern __shared__ float sm[];
    float* Ws = sm;                 // 128*128
    float* As = sm + 128 * 128;     // 64*128
    int tid = threadIdx.x;

    float4* Ws4 = (float4*)Ws;
    const float4* W4 = (const float4*)W;
#pragma unroll
    for (int i = tid; i < 128 * 32; i += 256) Ws4[i] = W4[i];

    int rbase = blockIdx.x * 64;
    float4* As4 = (float4*)As;
    const float4* A4 = (const float4*)A;
    for (int i = tid; i < 64 * 32; i += 256) {
        int r = rbase + (i >> 5);
        As4[i] = (r < N) ? A4[r * 32 + (i & 31)] : make_float4(0.f, 0.f, 0.f, 0.f);
    }
    __syncthreads();

    int cx = tid & 31;   // float4 column group: cols [4cx, 4cx+4)
    int rx = tid >> 5;   // row group: rows [rbase+8rx, rbase+8rx+8)
    float4 acc[8];
#pragma unroll
    for (int r = 0; r < 8; r++) acc[r] = make_float4(0.f, 0.f, 0.f, 0.f);

    const float* Arow = As + (rx * 8) * 128;
#pragma unroll 4
    for (int k = 0; k < 128; k++) {
        float4 w = Ws4[k * 32 + cx];
#pragma unroll
        for (int r = 0; r < 8; r++) {
            float a = Arow[r * 128 + k];
            acc[r].x += a * w.x;
            acc[r].y += a * w.y;
            acc[r].z += a * w.z;
            acc[r].w += a * w.w;
        }
    }

    float alpha = pa[0];
    float4 bb = ((const float4*)b)[cx];
#pragma unroll
    for (int r = 0; r < 8; r++) {
        int row = rbase + rx * 8 + r;
        if (row < N) {
            float4 z;
            z.x = acc[r].x + bb.x;
            z.y = acc[r].y + bb.y;
            z.z = acc[r].z + bb.z;
            z.w = acc[r].w + bb.w;
            z.x = (z.x >= 0.f) ? z.x : alpha * z.x;
            z.y = (z.y >= 0.f) ? z.y : alpha * z.y;
            z.z = (z.z >= 0.f) ? z.z : alpha * z.z;
            z.w = (z.w >= 0.f) ? z.w : alpha * z.w;
            ((float4*)out)[row * 32 + cx] = z;
        }
    }
}

// ---------------- launch ----------------
extern "C" void kernel_launch(void* const* d_in, const int* in_sizes, int n_in,
                              void* d_out, int out_size) {
    const float* x   = (const float*)d_in[0];
    const int*   src = (const int*)d_in[1];
    const int*   dst = (const int*)d_in[2];
    const float* W1  = (const float*)d_in[3];
    const float* b1  = (const float*)d_in[4];
    const float* W2  = (const float*)d_in[5];
    const float* b2  = (const float*)d_in[6];
    const float* pa  = (const float*)d_in[7];
    float* out = (float*)d_out;

    const int N = NN;
    const int E = EE;

    float *agg, *h;
    cudaGetSymbolAddress((void**)&agg, g_agg);
    cudaGetSymbolAddress((void**)&h, g_h);

    const int SMEM = (128 * 128 + 64 * 128) * 4;  // 96KB
    cudaFuncSetAttribute(k_gemm, cudaFuncAttributeMaxDynamicSharedMemorySize, SMEM);

    // Build CSR (in-edges grouped by dst) + out-degree normalization
    k_init<<<(N + 255) / 256, 256>>>(N);
    k_deg<<<(E + 255) / 256, 256>>>(src, dst, E);
    k_inv<<<(N + 255) / 256, 256>>>(N);
    k_scan<<<1, 1024>>>(N, E);
    k_scatter<<<(E + 255) / 256, 256>>>(src, dst, E);

    dim3 gt(32, 8);
    int gblocks = (N + 7) / 8;
    int mblocks = (N + 63) / 64;

    // Layer 1
    k_gather<<<gblocks, gt>>>((const float4*)x, (float4*)agg, N);
    k_gemm<<<mblocks, 256, SMEM>>>(agg, W1, b1, pa, h, N);
    // Layer 2
    k_gather<<<gblocks, gt>>>((const float4*)h, (float4*)agg, N);
    k_gemm<<<mblocks, 256, SMEM>>>(agg, W2, b2, pa, out, N);
}

// round 2
// speedup vs baseline: 1.2174x; 1.2174x over previous
#include <cuda_runtime.h>

#define NN 100000
#define EE 1600000
#define DD 128
#define NBLK ((NN + 1023) / 1024)   // 98 scan blocks

// ---------------- static device scratch (no allocation allowed) ----------------
__device__ float g_agg[NN * DD];      // SpMM output / GEMM input
__device__ float g_h[NN * DD];        // layer-1 output
__device__ int   g_outdeg[NN];
__device__ int   g_indeg[NN];
__device__ int   g_rowptr[NN + 1];
__device__ int   g_cursor[NN];
__device__ int   g_colidx[EE];
__device__ float g_inv[NN];
__device__ int   g_bsum[NBLK];
__device__ int   g_boff[NBLK];

// ---------------- f32x2 packed-math helpers ----------------
#define FMA_F32X2(d, a, b, c) \
    asm("fma.rn.f32x2 %0, %1, %2, %3;" : "=l"(d) : "l"(a), "l"(b), "l"(c))
#define DUP_F32X2(d, s) \
    asm("mov.b64 %0, {%1, %1};" : "=l"(d) : "r"(__float_as_int(s)))
#define UNPACK_F32X2(lo, hi, in) \
    asm("mov.b64 {%0, %1}, %2;" : "=r"(lo), "=r"(hi) : "l"(in))

// ---------------- build: degrees ----------------
__global__ void k_init(int N) {
    int i = blockIdx.x * blockDim.x + threadIdx.x;
    if (i < N) { g_outdeg[i] = 0; g_indeg[i] = 0; }
}

__global__ void k_deg(const int* __restrict__ src, const int* __restrict__ dst, int E) {
    int e = blockIdx.x * blockDim.x + threadIdx.x;
    if (e < E) {
        atomicAdd(&g_outdeg[src[e]], 1);
        atomicAdd(&g_indeg[dst[e]], 1);
    }
}

__global__ void k_inv(int N) {
    int i = blockIdx.x * blockDim.x + threadIdx.x;
    if (i < N) {
        int d = g_outdeg[i];
        g_inv[i] = 1.0f / (float)(d > 1 ? d : 1);
    }
}

// ---------------- build: parallel exclusive scan of in-degrees ----------------
// Stage 1: per-block (1024) scan, write local exclusive prefix + block total.
__global__ void k_scan1(int N) {
    __shared__ int s_w[32];
    int tid = threadIdx.x, lane = tid & 31, wid = tid >> 5;
    int i = blockIdx.x * 1024 + tid;
    int v = (i < N) ? g_indeg[i] : 0;
    int incl = v;
#pragma unroll
    for (int off = 1; off < 32; off <<= 1) {
        int t = __shfl_up_sync(0xffffffffu, incl, off);
        if (lane >= off) incl += t;
    }
    if (lane == 31) s_w[wid] = incl;
    __syncthreads();
    if (wid == 0) {
        int s = s_w[lane];
        int si = s;
#pragma unroll
        for (int off = 1; off < 32; off <<= 1) {
            int t = __shfl_up_sync(0xffffffffu, si, off);
            if (lane >= off) si += t;
        }
        s_w[lane] = si - s;  // exclusive prefix of warp sums
    }
    __syncthreads();
    int excl = incl - v + s_w[wid];
    if (i < N) g_rowptr[i] = excl;              // block-local for now
    if (tid == 1023) g_bsum[blockIdx.x] = s_w[31] + incl;  // block total
}

// Stage 2: exclusive scan of NBLK block totals (tiny, one block).
__global__ void k_scan2() {
    __shared__ int s[NBLK];
    int tid = threadIdx.x;
    if (tid < NBLK) s[tid] = g_bsum[tid];
    __syncthreads();
    if (tid == 0) {
        int run = 0;
        for (int b = 0; b < NBLK; b++) { int t = s[b]; s[b] = run; run += t; }
    }
    __syncthreads();
    if (tid < NBLK) g_boff[tid] = s[tid];
}

// Stage 3: add block offsets, materialize rowptr + cursor.
__global__ void k_scan3(int N, int E) {
    int i = blockIdx.x * blockDim.x + threadIdx.x;
    if (i < N) {
        int v = g_rowptr[i] + g_boff[i >> 10];
        g_rowptr[i] = v;
        g_cursor[i] = v;
    }
    if (i == 0) g_rowptr[N] = E;
}

// ---------------- build: scatter edges into CSR ----------------
__global__ void k_scatter(const int* __restrict__ src, const int* __restrict__ dst, int E) {
    int e = blockIdx.x * blockDim.x + threadIdx.x;
    if (e < E) {
        int p = atomicAdd(&g_cursor[dst[e]], 1);
        g_colidx[p] = src[e];
    }
}

// ---------------- SpMM gather: out[dst] = sum_{src in-edges} x[src] * inv[src] ----------------
__global__ void k_gather(const float4* __restrict__ xin, float4* __restrict__ out, int N) {
    int lane = threadIdx.x;
    int node = blockIdx.x * blockDim.y + threadIdx.y;
    if (node >= N) return;
    int beg = g_rowptr[node], end = g_rowptr[node + 1];
    float4 acc = make_float4(0.f, 0.f, 0.f, 0.f);
    for (int e = beg; e < end; e++) {
        int s = g_colidx[e];
        float sc = g_inv[s];
        float4 v = xin[s * 32 + lane];
        acc.x += v.x * sc;
        acc.y += v.y * sc;
        acc.z += v.z * sc;
        acc.w += v.w * sc;
    }
    out[node * 32 + lane] = acc;
}

// ---------------- dense GEMM + bias + PReLU (f32x2 packed rows) ----------------
// C[row] = prelu(A[row] @ W + b). 256 threads, 64 rows/block.
// A stored TRANSPOSED in smem (AT[k][row]) so row-pairs are contiguous u64.
// Thread (cx,rx): cx = 4-col group, rx = 8-row group (= 4 row-pairs).
// acc[p][c] = f32x2 over rows (2p, 2p+1) of column c.
__global__ void k_gemm(const float* __restrict__ A, const float* __restrict__ W,
                       const float* __restrict__ b, const float* __restrict__ pa,
                       float* __restrict__ out, int N) {
    extern __shared__ float sm[];
    float* Ws = sm;                  // 128*128
    float* AT = sm + 128 * 128;      // [128 k][64 rows]
    int tid = threadIdx.x;

    float4* Ws4 = (float4*)Ws;
    const float4* W4 = (const float4*)W;
#pragma unroll
    for (int i = tid; i < 128 * 32; i += 256) Ws4[i] = W4[i];

    int rbase = blockIdx.x * 64;
    const float4* A4 = (const float4*)A;
    for (int i = tid; i < 64 * 32; i += 256) {
        int r = i >> 5, c4 = i & 31;
        float4 v = (rbase + r < N) ? A4[(rbase + r) * 32 + c4]
                                   : make_float4(0.f, 0.f, 0.f, 0.f);
        AT[(c4 * 4 + 0) * 64 + r] = v.x;
        AT[(c4 * 4 + 1) * 64 + r] = v.y;
        AT[(c4 * 4 + 2) * 64 + r] = v.z;
        AT[(c4 * 4 + 3) * 64 + r] = v.w;
    }
    __syncthreads();

    int cx = tid & 31;   // column group: cols [4cx, 4cx+4)
    int rx = tid >> 5;   // row group: rows [rbase+8rx, rbase+8rx+8)

    unsigned long long acc[4][4];
#pragma unroll
    for (int p = 0; p < 4; p++)
#pragma unroll
        for (int c = 0; c < 4; c++) acc[p][c] = 0ull;

#pragma unroll 4
    for (int k = 0; k < 128; k++) {
        float4 w = Ws4[k * 32 + cx];
        unsigned long long wd0, wd1, wd2, wd3;
        DUP_F32X2(wd0, w.x);
        DUP_F32X2(wd1, w.y);
        DUP_F32X2(wd2, w.z);
        DUP_F32X2(wd3, w.w);
        const unsigned long long* a2 =
            (const unsigned long long*)(AT + k * 64 + rx * 8);
#pragma unroll
        for (int p = 0; p < 4; p++) {
            unsigned long long av = a2[p];
            FMA_F32X2(acc[p][0], av, wd0, acc[p][0]);
            FMA_F32X2(acc[p][1], av, wd1, acc[p][1]);
            FMA_F32X2(acc[p][2], av, wd2, acc[p][2]);
            FMA_F32X2(acc[p][3], av, wd3, acc[p][3]);
        }
    }

    float alpha = pa[0];
    float4 bb = ((const float4*)b)[cx];
#pragma unroll
    for (int p = 0; p < 4; p++) {
        int row0 = rbase + rx * 8 + 2 * p;
        int lo, hi;
        float4 z0, z1;
        UNPACK_F32X2(lo, hi, acc[p][0]); z0.x = __int_as_float(lo); z1.x = __int_as_float(hi);
        UNPACK_F32X2(lo, hi, acc[p][1]); z0.y = __int_as_float(lo); z1.y = __int_as_float(hi);
        UNPACK_F32X2(lo, hi, acc[p][2]); z0.z = __int_as_float(lo); z1.z = __int_as_float(hi);
        UNPACK_F32X2(lo, hi, acc[p][3]); z0.w = __int_as_float(lo); z1.w = __int_as_float(hi);

        z0.x += bb.x; z0.y += bb.y; z0.z += bb.z; z0.w += bb.w;
        z1.x += bb.x; z1.y += bb.y; z1.z += bb.z; z1.w += bb.w;
        z0.x = (z0.x >= 0.f) ? z0.x : alpha * z0.x;
        z0.y = (z0.y >= 0.f) ? z0.y : alpha * z0.y;
        z0.z = (z0.z >= 0.f) ? z0.z : alpha * z0.z;
        z0.w = (z0.w >= 0.f) ? z0.w : alpha * z0.w;
        z1.x = (z1.x >= 0.f) ? z1.x : alpha * z1.x;
        z1.y = (z1.y >= 0.f) ? z1.y : alpha * z1.y;
        z1.z = (z1.z >= 0.f) ? z1.z : alpha * z1.z;
        z1.w = (z1.w >= 0.f) ? z1.w : alpha * z1.w;

        if (row0 < N)     ((float4*)out)[row0 * 32 + cx] = z0;
        if (row0 + 1 < N) ((float4*)out)[(row0 + 1) * 32 + cx] = z1;
    }
}

// ---------------- launch ----------------
extern "C" void kernel_launch(void* const* d_in, const int* in_sizes, int n_in,
                              void* d_out, int out_size) {
    const float* x   = (const float*)d_in[0];
    const int*   src = (const int*)d_in[1];
    const int*   dst = (const int*)d_in[2];
    const float* W1  = (const float*)d_in[3];
    const float* b1  = (const float*)d_in[4];
    const float* W2  = (const float*)d_in[5];
    const float* b2  = (const float*)d_in[6];
    const float* pa  = (const float*)d_in[7];
    float* out = (float*)d_out;

    const int N = NN;
    const int E = EE;

    float *agg, *h;
    cudaGetSymbolAddress((void**)&agg, g_agg);
    cudaGetSymbolAddress((void**)&h, g_h);

    const int SMEM = (128 * 128 + 64 * 128) * 4;  // 96KB
    cudaFuncSetAttribute(k_gemm, cudaFuncAttributeMaxDynamicSharedMemorySize, SMEM);

    // Build CSR (in-edges grouped by dst) + out-degree normalization
    k_init<<<(N + 255) / 256, 256>>>(N);
    k_deg<<<(E + 255) / 256, 256>>>(src, dst, E);
    k_inv<<<(N + 255) / 256, 256>>>(N);
    k_scan1<<<NBLK, 1024>>>(N);
    k_scan2<<<1, 128>>>();
    k_scan3<<<(N + 255) / 256, 256>>>(N, E);
    k_scatter<<<(E + 255) / 256, 256>>>(src, dst, E);

    dim3 gt(32, 8);
    int gblocks = (N + 7) / 8;
    int mblocks = (N + 63) / 64;

    // Layer 1
    k_gather<<<gblocks, gt>>>((const float4*)x, (float4*)agg, N);
    k_gemm<<<mblocks, 256, SMEM>>>(agg, W1, b1, pa, h, N);
    // Layer 2
    k_gather<<<gblocks, gt>>>((const float4*)h, (float4*)agg, N);
    k_gemm<<<mblocks, 256, SMEM>>>(agg, W2, b2, pa, out, N);
}

// round 4
// speedup vs baseline: 1.6729x; 1.3742x over previous
#include <cuda_runtime.h>
#include <cstdint>

#define NN 100000
#define EE 1600000
#define DD 128
#define NBLK ((NN + 1023) / 1024)   // 98 scan blocks

// ---------------- static device scratch (no allocation allowed) ----------------
__device__ float g_agg[NN * DD];       // SpMM output / GEMM input
__device__ float g_h[NN * DD];         // layer-1 output
__device__ float g_wfrag1[16 * 16 * 32 * 2];  // W1 mma B-fragment table (64KB)
__device__ float g_wfrag2[16 * 16 * 32 * 2];  // W2 fragment table
__device__ int   g_outdeg[NN];
__device__ int   g_indeg[NN];
__device__ int   g_rowptr[NN + 1];
__device__ int   g_cursor[NN];
__device__ int   g_colidx[EE];
__device__ float g_inv[NN];
__device__ int   g_bsum[NBLK];
__device__ int   g_boff[NBLK];

__device__ __forceinline__ uint32_t f2tf32(float x) {
    uint32_t r;
    asm("cvt.rna.tf32.f32 %0, %1;" : "=r"(r) : "f"(x));
    return r;
}

#define MMA_TF32(c0, c1, c2, c3, a0, a1, a2, a3, b0, b1) \
    asm volatile("mma.sync.aligned.m16n8k8.row.col.f32.tf32.tf32.f32 " \
        "{%0,%1,%2,%3}, {%4,%5,%6,%7}, {%8,%9}, {%0,%1,%2,%3};" \
        : "+f"(c0), "+f"(c1), "+f"(c2), "+f"(c3) \
        : "r"(a0), "r"(a1), "r"(a2), "r"(a3), "r"(b0), "r"(b1))

// ---------------- build: degrees ----------------
__global__ void k_init(int N) {
    int i = blockIdx.x * blockDim.x + threadIdx.x;
    if (i < N) { g_outdeg[i] = 0; g_indeg[i] = 0; }
}

__global__ void k_deg(const int* __restrict__ src, const int* __restrict__ dst, int E) {
    int e = blockIdx.x * blockDim.x + threadIdx.x;
    if (e < E) {
        atomicAdd(&g_outdeg[src[e]], 1);
        atomicAdd(&g_indeg[dst[e]], 1);
    }
}

__global__ void k_inv(int N) {
    int i = blockIdx.x * blockDim.x + threadIdx.x;
    if (i < N) {
        int d = g_outdeg[i];
        g_inv[i] = 1.0f / (float)(d > 1 ? d : 1);
    }
}

// ---------------- build: parallel exclusive scan ----------------
__global__ void k_scan1(int N) {
    __shared__ int s_w[32];
    int tid = threadIdx.x, lane = tid & 31, wid = tid >> 5;
    int i = blockIdx.x * 1024 + tid;
    int v = (i < N) ? g_indeg[i] : 0;
    int incl = v;
#pragma unroll
    for (int off = 1; off < 32; off <<= 1) {
        int t = __shfl_up_sync(0xffffffffu, incl, off);
        if (lane >= off) incl += t;
    }
    if (lane == 31) s_w[wid] = incl;
    __syncthreads();
    if (wid == 0) {
        int s = s_w[lane];
        int si = s;
#pragma unroll
        for (int off = 1; off < 32; off <<= 1) {
            int t = __shfl_up_sync(0xffffffffu, si, off);
            if (lane >= off) si += t;
        }
        s_w[lane] = si - s;
    }
    __syncthreads();
    int excl = incl - v + s_w[wid];
    if (i < N) g_rowptr[i] = excl;
    if (tid == 1023) g_bsum[blockIdx.x] = s_w[31] + incl;
}

__global__ void k_scan2() {
    __shared__ int s[NBLK];
    int tid = threadIdx.x;
    if (tid < NBLK) s[tid] = g_bsum[tid];
    __syncthreads();
    if (tid == 0) {
        int run = 0;
        for (int b = 0; b < NBLK; b++) { int t = s[b]; s[b] = run; run += t; }
    }
    __syncthreads();
    if (tid < NBLK) g_boff[tid] = s[tid];
}

__global__ void k_scan3(int N, int E) {
    int i = blockIdx.x * blockDim.x + threadIdx.x;
    if (i < N) {
        int v = g_rowptr[i] + g_boff[i >> 10];
        g_rowptr[i] = v;
        g_cursor[i] = v;
    }
    if (i == 0) g_rowptr[N] = E;
}

__global__ void k_scatter(const int* __restrict__ src, const int* __restrict__ dst, int E) {
    int e = blockIdx.x * blockDim.x + threadIdx.x;
    if (e < E) {
        int p = atomicAdd(&g_cursor[dst[e]], 1);
        g_colidx[p] = src[e];
    }
}

// ---------------- pack W into mma B-fragment table ----------------
// frag[(ks*16 + nt)*32 + lane] = float2{ W[ks*8 + lane%4][nt*8 + lane/4],
//                                        W[ks*8 + 4 + lane%4][nt*8 + lane/4] }  (tf32)
__global__ void k_wfrag(const float* __restrict__ W, float* __restrict__ frag) {
    int idx = blockIdx.x * 256 + threadIdx.x;   // 0..8191
    if (idx >= 8192) return;
    int lane = idx & 31, nt = (idx >> 5) & 15, ks = idx >> 9;
    int k0 = ks * 8, col = nt * 8 + (lane >> 2), r = lane & 3;
    float2 o;
    o.x = __uint_as_float(f2tf32(W[(k0 + r) * DD + col]));
    o.y = __uint_as_float(f2tf32(W[(k0 + 4 + r) * DD + col]));
    ((float2*)frag)[idx] = o;
}

// ---------------- SpMM gather ----------------
__global__ void k_gather(const float4* __restrict__ xin, float4* __restrict__ out, int N) {
    int lane = threadIdx.x;
    int node = blockIdx.x * blockDim.y + threadIdx.y;
    if (node >= N) return;
    int beg = g_rowptr[node], end = g_rowptr[node + 1];
    float4 acc = make_float4(0.f, 0.f, 0.f, 0.f);
    for (int e = beg; e < end; e++) {
        int s = g_colidx[e];
        float sc = g_inv[s];
        float4 v = xin[s * 32 + lane];
        acc.x += v.x * sc;
        acc.y += v.y * sc;
        acc.z += v.z * sc;
        acc.w += v.w * sc;
    }
    out[node * 32 + lane] = acc;
}

// ---------------- tf32 mma.sync GEMM + bias + PReLU ----------------
// CTA: 64 rows x 128 cols, 8 warps, warp tile 16x64.
// A tile in smem (stride 132: conflict-free frag loads). B frags from gmem table (L1-hit).
#define ASTRIDE 132
__global__ __launch_bounds__(256, 2)
void k_gemm_mma(const float* __restrict__ A, const float* __restrict__ wfrag,
                const float* __restrict__ bias, const float* __restrict__ pa,
                float* __restrict__ out, int N) {
    __shared__ float As[64 * ASTRIDE];
    int tid = threadIdx.x;
    int lane = tid & 31, wid = tid >> 5;
    int rowgrp = wid & 3, colgrp = wid >> 2;
    int rbase = blockIdx.x * 64;

    // Fill A tile (tf32-converted), STS.128.
    const float4* A4 = (const float4*)A;
    for (int i = tid; i < 64 * 32; i += 256) {
        int r = i >> 5, c4 = i & 31;
        int row = rbase + r;
        if (row >= N) row = N - 1;   // clamp; extra rows never stored
        float4 v = A4[row * 32 + c4];
        float4 t;
        t.x = __uint_as_float(f2tf32(v.x));
        t.y = __uint_as_float(f2tf32(v.y));
        t.z = __uint_as_float(f2tf32(v.z));
        t.w = __uint_as_float(f2tf32(v.w));
        *(float4*)&As[r * ASTRIDE + c4 * 4] = t;
    }
    __syncthreads();

    float c[8][4];
#pragma unroll
    for (int nt = 0; nt < 8; nt++)
#pragma unroll
        for (int j = 0; j < 4; j++) c[nt][j] = 0.f;

    const float* Ab = As + (rowgrp * 16 + (lane >> 2)) * ASTRIDE + (lane & 3);
    const float2* wf = (const float2*)wfrag;

#pragma unroll
    for (int ks = 0; ks < 16; ks++) {
        int k0 = ks * 8;
        uint32_t a0 = __float_as_uint(Ab[k0]);
        uint32_t a1 = __float_as_uint(Ab[8 * ASTRIDE + k0]);
        uint32_t a2 = __float_as_uint(Ab[k0 + 4]);
        uint32_t a3 = __float_as_uint(Ab[8 * ASTRIDE + k0 + 4]);
        const float2* wk = wf + (ks * 16 + colgrp * 8) * 32 + lane;
#pragma unroll
        for (int nt = 0; nt < 8; nt++) {
            float2 bv = wk[nt * 32];
            MMA_TF32(c[nt][0], c[nt][1], c[nt][2], c[nt][3],
                     a0, a1, a2, a3,
                     __float_as_uint(bv.x), __float_as_uint(bv.y));
        }
    }

    // Epilogue: bias + PReLU, direct float2 stores.
    float alpha = pa[0];
    int r_lo = rbase + rowgrp * 16 + (lane >> 2);
    int r_hi = r_lo + 8;
#pragma unroll
    for (int nt = 0; nt < 8; nt++) {
        int col = colgrp * 64 + nt * 8 + (lane & 3) * 2;
        float2 bb = *(const float2*)(bias + col);
        float z0 = c[nt][0] + bb.x;
        float z1 = c[nt][1] + bb.y;
        float z2 = c[nt][2] + bb.x;
        float z3 = c[nt][3] + bb.y;
        z0 = (z0 >= 0.f) ? z0 : alpha * z0;
        z1 = (z1 >= 0.f) ? z1 : alpha * z1;
        z2 = (z2 >= 0.f) ? z2 : alpha * z2;
        z3 = (z3 >= 0.f) ? z3 : alpha * z3;
        if (r_lo < N) { float2 o = {z0, z1}; *(float2*)(out + r_lo * DD + col) = o; }
        if (r_hi < N) { float2 o = {z2, z3}; *(float2*)(out + r_hi * DD + col) = o; }
    }
}

// ---------------- launch ----------------
extern "C" void kernel_launch(void* const* d_in, const int* in_sizes, int n_in,
                              void* d_out, int out_size) {
    const float* x   = (const float*)d_in[0];
    const int*   src = (const int*)d_in[1];
    const int*   dst = (const int*)d_in[2];
    const float* W1  = (const float*)d_in[3];
    const float* b1  = (const float*)d_in[4];
    const float* W2  = (const float*)d_in[5];
    const float* b2  = (const float*)d_in[6];
    const float* pa  = (const float*)d_in[7];
    float* out = (float*)d_out;

    const int N = NN;
    const int E = EE;

    float *agg, *h, *wf1, *wf2;
    cudaGetSymbolAddress((void**)&agg, g_agg);
    cudaGetSymbolAddress((void**)&h, g_h);
    cudaGetSymbolAddress((void**)&wf1, g_wfrag1);
    cudaGetSymbolAddress((void**)&wf2, g_wfrag2);

    // Build CSR + normalization + W fragment tables
    k_init<<<(N + 255) / 256, 256>>>(N);
    k_deg<<<(E + 255) / 256, 256>>>(src, dst, E);
    k_inv<<<(N + 255) / 256, 256>>>(N);
    k_scan1<<<NBLK, 1024>>>(N);
    k_scan2<<<1, 128>>>();
    k_scan3<<<(N + 255) / 256, 256>>>(N, E);
    k_scatter<<<(E + 255) / 256, 256>>>(src, dst, E);
    k_wfrag<<<32, 256>>>(W1, wf1);
    k_wfrag<<<32, 256>>>(W2, wf2);

    dim3 gt(32, 8);
    int gblocks = (N + 7) / 8;
    int mblocks = (N + 63) / 64;   // 1563

    // Layer 1
    k_gather<<<gblocks, gt>>>((const float4*)x, (float4*)agg, N);
    k_gemm_mma<<<mblocks, 256>>>(agg, wf1, b1, pa, h, N);
    // Layer 2
    k_gather<<<gblocks, gt>>>((const float4*)h, (float4*)agg, N);
    k_gemm_mma<<<mblocks, 256>>>(agg, wf2, b2, pa, out, N);
}